// round 6
// baseline (speedup 1.0000x reference)
#include <cuda_runtime.h>
#include <cuda_fp16.h>
#include <cstdint>

#define D          256
#define NCODES     1024
#define ROWS_TOTAL 16384
#define BM         128
#define BN         256
#define NKCH       4         // K=256, chunks of 64
#define NITER      4         // NCODES / BN

#define ASTRIDE_B   160
#define A_STAGE     (BM * ASTRIDE_B)              // 20480
#define B_STAGE     (BN * ASTRIDE_B)              // 40960
#define STAGE_BYTES (A_STAGE + B_STAGE)           // 61440
#define B_OFF       A_STAGE
#define EHALF_OFF   (2 * STAGE_BYTES)             // 122880
#define SMEM_TOTAL  (EHALF_OFF + NCODES * 4)      // 126976

__device__ __half g_Xc[(size_t)ROWS_TOTAL * D];    // 8 MB  (hi only, interleaved)
__device__ __half g_Ec[(size_t)NCODES * D];        // 0.5 MB
__device__ float  g_e_half[NCODES];
__device__ float  g_S[(size_t)ROWS_TOTAL * NCODES];   // 64 MB scores
__device__ int    g_maxEsq_bits;

__device__ __forceinline__ int ilv16(int k) {      // fragment interleave within 16-group
    return 4 * ((k & 7) >> 1) + 2 * (k >> 3) + (k & 1);
}

__global__ void init_kernel() { g_maxEsq_bits = 0; }

__global__ void prep_x(const float* __restrict__ X) {
    for (int idx = blockIdx.x * blockDim.x + threadIdx.x;
         idx < ROWS_TOTAL * D; idx += gridDim.x * blockDim.x) {
        int m = idx >> 8, k = idx & 255;
        g_Xc[(size_t)m * D + (k >> 4) * 16 + ilv16(k & 15)] = __float2half_rn(X[idx]);
    }
}

__global__ void prep_e(const float* __restrict__ E) {
    for (int idx = blockIdx.x * blockDim.x + threadIdx.x;
         idx < NCODES * D; idx += gridDim.x * blockDim.x) {
        int n = idx >> 8, k = idx & 255;
        g_Ec[(size_t)n * D + (k >> 4) * 16 + ilv16(k & 15)] = __float2half_rn(E[idx]);
    }
}

__global__ void e_half_kernel(const float* __restrict__ E) {
    int n = blockIdx.x * blockDim.x + threadIdx.x;
    if (n >= NCODES) return;
    const float4* row = reinterpret_cast<const float4*>(E + (size_t)n * D);
    float s = 0.f;
#pragma unroll
    for (int i = 0; i < D / 4; i++) {
        float4 v = row[i];
        s += v.x * v.x + v.y * v.y + v.z * v.z + v.w * v.w;
    }
    g_e_half[n] = 0.5f * s;
    atomicMax(&g_maxEsq_bits, __float_as_int(s));   // s >= 0: int-bits monotonic
}

static __device__ __forceinline__ uint32_t smem_u32(const void* p) {
    uint32_t a;
    asm("{ .reg .u64 t; cvta.to.shared.u64 t, %1; cvt.u32.u64 %0, t; }" : "=r"(a) : "l"(p));
    return a;
}
#define CP16(dst, src) asm volatile("cp.async.cg.shared.global [%0], [%1], 16;" :: "r"(dst), "l"(src) : "memory")
#define LDS64(r0, r1, a) asm volatile("ld.shared.v2.b32 {%0,%1}, [%2];" : "=r"(r0), "=r"(r1) : "r"(a))
#define MMA_F16(c, a, b) \
    asm volatile("mma.sync.aligned.m16n8k16.row.col.f32.f16.f16.f32 " \
                 "{%0,%1,%2,%3}, {%4,%5,%6,%7}, {%8,%9}, {%0,%1,%2,%3};" \
                 : "+f"((c)[0]), "+f"((c)[1]), "+f"((c)[2]), "+f"((c)[3]) \
                 : "r"((a)[0]), "r"((a)[1]), "r"((a)[2]), "r"((a)[3]), "r"((b)[0]), "r"((b)[1]))

__global__ __launch_bounds__(256, 1)
void vq_mma(float* __restrict__ dummy) {
    extern __shared__ char smem[];
    const uint32_t sb = smem_u32(smem);
    float* ehs = (float*)(smem + EHALF_OFF);

    const int tid  = threadIdx.x;
    const int lane = tid & 31, wid = tid >> 5;
    const int wm = wid & 1, wn = wid >> 1;
    const int g = lane >> 2, t = lane & 3;
    const int row0 = blockIdx.x * BM;

    for (int i = tid; i < NCODES; i += 256) ehs[i] = g_e_half[i];

    const int urow = tid >> 3, uj = tid & 7;
    const char* aSrc0 = (const char*)(g_Xc + (size_t)(row0 + urow) * D) + uj * 16;
    const uint32_t aDst0 = sb + urow * ASTRIDE_B + uj * 16;
    const uint32_t bDst0 = sb + B_OFF + urow * ASTRIDE_B + uj * 16;

    const uint32_t aLds0 = sb + (uint32_t)((wm * 64 + g) * ASTRIDE_B + t * 8);
    const uint32_t bLds0 = sb + (uint32_t)(B_OFF + (wn * 64 + g) * ASTRIDE_B + t * 8);

    float* Sblk = g_S + (size_t)row0 * NCODES;

    for (int ni = 0; ni < NITER; ni++) {
        const int n0 = ni * BN;
        const char* bSrc0 = (const char*)(g_Ec + (size_t)(n0 + urow) * D) + uj * 16;

        float acc[4][8][4];
#pragma unroll
        for (int mi = 0; mi < 4; mi++)
#pragma unroll
            for (int nj = 0; nj < 8; nj++)
#pragma unroll
                for (int q = 0; q < 4; q++) acc[mi][nj][q] = 0.f;

        {   // prologue: chunk 0 -> stage 0
#pragma unroll
            for (int i = 0; i < 4; i++) CP16(aDst0 + i * (32 * ASTRIDE_B), aSrc0 + i * 16384);
#pragma unroll
            for (int i = 0; i < 8; i++) CP16(bDst0 + i * (32 * ASTRIDE_B), bSrc0 + i * 16384);
            asm volatile("cp.async.commit_group;" ::: "memory");
        }

        for (int kc = 0; kc < NKCH; kc++) {
            const uint32_t st = (uint32_t)(kc & 1) * STAGE_BYTES;

            if (kc + 1 < NKCH) {
                const int kn = kc + 1;
                const uint32_t nst = (uint32_t)(kn & 1) * STAGE_BYTES;
#pragma unroll
                for (int i = 0; i < 4; i++)
                    CP16(nst + aDst0 + i * (32 * ASTRIDE_B), aSrc0 + kn * 128 + i * 16384);
#pragma unroll
                for (int i = 0; i < 8; i++)
                    CP16(nst + bDst0 + i * (32 * ASTRIDE_B), bSrc0 + kn * 128 + i * 16384);
                asm volatile("cp.async.commit_group;" ::: "memory");
                asm volatile("cp.async.wait_group 1;" ::: "memory");
            } else {
                asm volatile("cp.async.wait_group 0;" ::: "memory");
            }
            __syncthreads();

#pragma unroll
            for (int s = 0; s < 4; s++) {
                uint32_t a[4][4];
#pragma unroll
                for (int mi = 0; mi < 4; mi++) {
                    uint32_t ad = st + aLds0 + (uint32_t)(mi * 16 * ASTRIDE_B + s * 32);
                    LDS64(a[mi][0], a[mi][2], ad);
                    LDS64(a[mi][1], a[mi][3], ad + 8 * ASTRIDE_B);
                }
                uint32_t b[8][2];
#pragma unroll
                for (int nj = 0; nj < 8; nj++) {
                    uint32_t bd = st + bLds0 + (uint32_t)(nj * 8 * ASTRIDE_B + s * 32);
                    LDS64(b[nj][0], b[nj][1], bd);
                }
#pragma unroll
                for (int mi = 0; mi < 4; mi++)
#pragma unroll
                    for (int nj = 0; nj < 8; nj++)
                        MMA_F16(acc[mi][nj], a[mi], b[nj]);
            }
            __syncthreads();
        }

        // ---- epilogue: dump scores ŝ = xh·eh − ½‖e‖² to global scratch ----
#pragma unroll
        for (int mi = 0; mi < 4; mi++)
#pragma unroll
            for (int nj = 0; nj < 8; nj++)
#pragma unroll
                for (int q = 0; q < 4; q++) {
                    int r = wm * 64 + mi * 16 + g + 8 * (q >> 1);
                    int n = n0 + wn * 64 + nj * 8 + 2 * t + (q & 1);
                    Sblk[(size_t)r * NCODES + n] = acc[mi][nj][q] - ehs[n];
                }
    }
    if (tid == 1024) dummy[0] = 0.f;   // never true; keeps param
}

// ---- pass 2: one warp per row — certified argmax + fp64 rescue of candidates ----
__global__ __launch_bounds__(256)
void rescue(const float* __restrict__ X, const float* __restrict__ E,
            float* __restrict__ out) {
    const int lane = threadIdx.x & 31;
    const int row  = blockIdx.x * 8 + (threadIdx.x >> 5);

    const float4* S4 = reinterpret_cast<const float4*>(g_S + (size_t)row * NCODES);
    float4 s4[8];
    float m1 = -3.4e38f;
#pragma unroll
    for (int j = 0; j < 8; j++) {
        s4[j] = S4[lane + 32 * j];
        m1 = fmaxf(m1, fmaxf(fmaxf(s4[j].x, s4[j].y), fmaxf(s4[j].z, s4[j].w)));
    }
#pragma unroll
    for (int off = 16; off > 0; off >>= 1)
        m1 = fmaxf(m1, __shfl_xor_sync(0xffffffffu, m1, off));

    const float4* X4 = reinterpret_cast<const float4*>(X + (size_t)row * D);
    float4 x0 = X4[lane], x1 = X4[lane + 32];
    float xsq = x0.x * x0.x + x0.y * x0.y + x0.z * x0.z + x0.w * x0.w
              + x1.x * x1.x + x1.y * x1.y + x1.z * x1.z + x1.w * x1.w;
#pragma unroll
    for (int off = 16; off > 0; off >>= 1)
        xsq += __shfl_xor_sync(0xffffffffu, xsq, off);

    const float maxEsq = __int_as_float(g_maxEsq_bits);
    const float M = 0.002f * sqrtf(xsq * maxEsq) + 0.03f;   // certified margin
    const float thr = m1 - M;

    double bestv = -1e300;
    int    besti = 0;
#pragma unroll
    for (int j = 0; j < 8; j++) {
        const float sv[4] = { s4[j].x, s4[j].y, s4[j].z, s4[j].w };
#pragma unroll
        for (int c = 0; c < 4; c++) {
            unsigned bal = __ballot_sync(0xffffffffu, sv[c] >= thr);
            while (bal) {
                int b = __ffs(bal) - 1; bal &= bal - 1;
                int idx = 4 * b + 128 * j + c;
                const float4* E4r = reinterpret_cast<const float4*>(E + (size_t)idx * D);
                float4 e0 = E4r[lane], e1 = E4r[lane + 32];
                double sc =
                    (double)x0.x * e0.x + (double)x0.y * e0.y + (double)x0.z * e0.z + (double)x0.w * e0.w +
                    (double)x1.x * e1.x + (double)x1.y * e1.y + (double)x1.z * e1.z + (double)x1.w * e1.w
                    - 0.5 * ((double)e0.x * e0.x + (double)e0.y * e0.y + (double)e0.z * e0.z + (double)e0.w * e0.w +
                             (double)e1.x * e1.x + (double)e1.y * e1.y + (double)e1.z * e1.z + (double)e1.w * e1.w);
#pragma unroll
                for (int off = 16; off > 0; off >>= 1)
                    sc += __shfl_xor_sync(0xffffffffu, sc, off);
                if (sc > bestv || (sc == bestv && idx < besti)) { bestv = sc; besti = idx; }
            }
        }
    }

    const float4* Eb = reinterpret_cast<const float4*>(E + (size_t)besti * D);
    float4* O4 = reinterpret_cast<float4*>(out + (size_t)row * D);
    O4[lane]      = Eb[lane];
    O4[lane + 32] = Eb[lane + 32];
}

extern "C" void kernel_launch(void* const* d_in, const int* in_sizes, int n_in,
                              void* d_out, int out_size) {
    const float* x = (const float*)d_in[0];     // [16,1024,256] f32
    const float* E = (const float*)d_in[1];     // [1024,256]    f32
    float* out = (float*)d_out;

    init_kernel<<<1, 1>>>();
    e_half_kernel<<<(NCODES + 255) / 256, 256>>>(E);
    prep_e<<<256, 256>>>(E);
    prep_x<<<2048, 256>>>(x);

    cudaFuncSetAttribute(vq_mma, cudaFuncAttributeMaxDynamicSharedMemorySize, SMEM_TOTAL);
    vq_mma<<<ROWS_TOTAL / BM, 256, SMEM_TOTAL>>>(out);

    rescue<<<ROWS_TOTAL / 8, 256>>>(x, E, out);
}

// round 7
// speedup vs baseline: 1.1242x; 1.1242x over previous
#include <cuda_runtime.h>
#include <cuda_fp16.h>
#include <cstdint>

#define D          256
#define NCODES     1024
#define ROWS_TOTAL 16384
#define BM         128
#define BN         256
#define NKCH       4         // K=256, chunks of 64
#define NITER      4         // NCODES / BN

#define ASTRIDE_B   160
#define A_STAGE     (BM * ASTRIDE_B)              // 20480
#define B_STAGE     (BN * ASTRIDE_B)              // 40960
#define STAGE_BYTES (A_STAGE + B_STAGE)           // 61440
#define B_OFF       A_STAGE
#define EHALF_OFF   (2 * STAGE_BYTES)             // 122880
#define SMEM_TOTAL  (EHALF_OFF + NCODES * 4)      // 126976

__device__ __half g_Xc[(size_t)ROWS_TOTAL * D];    // 8 MB  (hi only, interleaved)
__device__ __half g_Ec[(size_t)NCODES * D];        // 0.5 MB
__device__ float  g_e_half[NCODES];
__device__ float  g_S[(size_t)ROWS_TOTAL * NCODES];   // 64 MB scores (L2-resident)
__device__ int    g_maxEsq_bits;

__device__ __forceinline__ constexpr int ilv16(int k) {   // fragment interleave in 16-group
    return 4 * ((k & 7) >> 1) + 2 * (k >> 3) + (k & 1);
}

__global__ void init_kernel() { g_maxEsq_bits = 0; }

// one thread converts one 16-element group: 4x LDG.128 -> 2x STG.128
__global__ void prep_x(const float* __restrict__ X) {
    int gi = blockIdx.x * blockDim.x + threadIdx.x;       // ROWS_TOTAL*16 groups
    const float4* src = reinterpret_cast<const float4*>(X) + (size_t)gi * 4;
    float4 v0 = src[0], v1 = src[1], v2 = src[2], v3 = src[3];
    float f[16] = { v0.x, v0.y, v0.z, v0.w, v1.x, v1.y, v1.z, v1.w,
                    v2.x, v2.y, v2.z, v2.w, v3.x, v3.y, v3.z, v3.w };
    __half h[16];
#pragma unroll
    for (int j = 0; j < 16; j++) h[ilv16(j)] = __float2half_rn(f[j]);
    uint4* dst = reinterpret_cast<uint4*>(g_Xc) + (size_t)gi * 2;
    dst[0] = reinterpret_cast<const uint4*>(h)[0];
    dst[1] = reinterpret_cast<const uint4*>(h)[1];
}

__global__ void prep_e(const float* __restrict__ E) {
    int gi = blockIdx.x * blockDim.x + threadIdx.x;       // NCODES*16 groups
    const float4* src = reinterpret_cast<const float4*>(E) + (size_t)gi * 4;
    float4 v0 = src[0], v1 = src[1], v2 = src[2], v3 = src[3];
    float f[16] = { v0.x, v0.y, v0.z, v0.w, v1.x, v1.y, v1.z, v1.w,
                    v2.x, v2.y, v2.z, v2.w, v3.x, v3.y, v3.z, v3.w };
    __half h[16];
#pragma unroll
    for (int j = 0; j < 16; j++) h[ilv16(j)] = __float2half_rn(f[j]);
    uint4* dst = reinterpret_cast<uint4*>(g_Ec) + (size_t)gi * 2;
    dst[0] = reinterpret_cast<const uint4*>(h)[0];
    dst[1] = reinterpret_cast<const uint4*>(h)[1];
}

__global__ void e_half_kernel(const float* __restrict__ E) {
    int n = blockIdx.x * blockDim.x + threadIdx.x;
    if (n >= NCODES) return;
    const float4* row = reinterpret_cast<const float4*>(E + (size_t)n * D);
    float s = 0.f;
#pragma unroll
    for (int i = 0; i < D / 4; i++) {
        float4 v = row[i];
        s += v.x * v.x + v.y * v.y + v.z * v.z + v.w * v.w;
    }
    g_e_half[n] = 0.5f * s;
    atomicMax(&g_maxEsq_bits, __float_as_int(s));   // s >= 0: int-bits monotonic
}

static __device__ __forceinline__ uint32_t smem_u32(const void* p) {
    uint32_t a;
    asm("{ .reg .u64 t; cvta.to.shared.u64 t, %1; cvt.u32.u64 %0, t; }" : "=r"(a) : "l"(p));
    return a;
}
#define CP16(dst, src) asm volatile("cp.async.cg.shared.global [%0], [%1], 16;" :: "r"(dst), "l"(src) : "memory")
#define LDS64(r0, r1, a) asm volatile("ld.shared.v2.b32 {%0,%1}, [%2];" : "=r"(r0), "=r"(r1) : "r"(a))
#define MMA_F16(c, a, b) \
    asm volatile("mma.sync.aligned.m16n8k16.row.col.f32.f16.f16.f32 " \
                 "{%0,%1,%2,%3}, {%4,%5,%6,%7}, {%8,%9}, {%0,%1,%2,%3};" \
                 : "+f"((c)[0]), "+f"((c)[1]), "+f"((c)[2]), "+f"((c)[3]) \
                 : "r"((a)[0]), "r"((a)[1]), "r"((a)[2]), "r"((a)[3]), "r"((b)[0]), "r"((b)[1]))

__global__ __launch_bounds__(256, 1)
void vq_mma() {
    extern __shared__ char smem[];
    const uint32_t sb = smem_u32(smem);
    float* ehs = (float*)(smem + EHALF_OFF);

    const int tid  = threadIdx.x;
    const int lane = tid & 31, wid = tid >> 5;
    const int wm = wid & 1, wn = wid >> 1;
    const int g = lane >> 2, t = lane & 3;
    const int row0 = blockIdx.x * BM;

    for (int i = tid; i < NCODES; i += 256) ehs[i] = g_e_half[i];

    const int urow = tid >> 3, uj = tid & 7;
    const char* aSrc0 = (const char*)(g_Xc + (size_t)(row0 + urow) * D) + uj * 16;
    const uint32_t aDst0 = sb + urow * ASTRIDE_B + uj * 16;
    const uint32_t bDst0 = sb + B_OFF + urow * ASTRIDE_B + uj * 16;

    const uint32_t aLds0 = sb + (uint32_t)((wm * 64 + g) * ASTRIDE_B + t * 8);
    const uint32_t bLds0 = sb + (uint32_t)(B_OFF + (wn * 64 + g) * ASTRIDE_B + t * 8);

    float* Sblk = g_S + (size_t)row0 * NCODES;

    for (int ni = 0; ni < NITER; ni++) {
        const int n0 = ni * BN;
        const char* bSrc0 = (const char*)(g_Ec + (size_t)(n0 + urow) * D) + uj * 16;

        float acc[4][8][4];
#pragma unroll
        for (int mi = 0; mi < 4; mi++)
#pragma unroll
            for (int nj = 0; nj < 8; nj++)
#pragma unroll
                for (int q = 0; q < 4; q++) acc[mi][nj][q] = 0.f;

        {   // prologue: chunk 0 -> stage 0
#pragma unroll
            for (int i = 0; i < 4; i++) CP16(aDst0 + i * (32 * ASTRIDE_B), aSrc0 + i * 16384);
#pragma unroll
            for (int i = 0; i < 8; i++) CP16(bDst0 + i * (32 * ASTRIDE_B), bSrc0 + i * 16384);
            asm volatile("cp.async.commit_group;" ::: "memory");
        }

        for (int kc = 0; kc < NKCH; kc++) {
            const uint32_t st = (uint32_t)(kc & 1) * STAGE_BYTES;

            if (kc + 1 < NKCH) {
                const int kn = kc + 1;
                const uint32_t nst = (uint32_t)(kn & 1) * STAGE_BYTES;
#pragma unroll
                for (int i = 0; i < 4; i++)
                    CP16(nst + aDst0 + i * (32 * ASTRIDE_B), aSrc0 + kn * 128 + i * 16384);
#pragma unroll
                for (int i = 0; i < 8; i++)
                    CP16(nst + bDst0 + i * (32 * ASTRIDE_B), bSrc0 + kn * 128 + i * 16384);
                asm volatile("cp.async.commit_group;" ::: "memory");
                asm volatile("cp.async.wait_group 1;" ::: "memory");
            } else {
                asm volatile("cp.async.wait_group 0;" ::: "memory");
            }
            __syncthreads();

#pragma unroll
            for (int s = 0; s < 4; s++) {
                uint32_t a[4][4];
#pragma unroll
                for (int mi = 0; mi < 4; mi++) {
                    uint32_t ad = st + aLds0 + (uint32_t)(mi * 16 * ASTRIDE_B + s * 32);
                    LDS64(a[mi][0], a[mi][2], ad);
                    LDS64(a[mi][1], a[mi][3], ad + 8 * ASTRIDE_B);
                }
                uint32_t b[8][2];
#pragma unroll
                for (int nj = 0; nj < 8; nj++) {
                    uint32_t bd = st + bLds0 + (uint32_t)(nj * 8 * ASTRIDE_B + s * 32);
                    LDS64(b[nj][0], b[nj][1], bd);
                }
#pragma unroll
                for (int mi = 0; mi < 4; mi++)
#pragma unroll
                    for (int nj = 0; nj < 8; nj++)
                        MMA_F16(acc[mi][nj], a[mi], b[nj]);
            }
            __syncthreads();
        }

        // ---- epilogue: coalesced float2 score dump (quad t=0..3 -> 32B sectors) ----
#pragma unroll
        for (int mi = 0; mi < 4; mi++)
#pragma unroll
            for (int qh = 0; qh < 2; qh++) {
                const int r = wm * 64 + mi * 16 + g + 8 * qh;
                float* Srow = Sblk + (size_t)r * NCODES;
#pragma unroll
                for (int nj = 0; nj < 8; nj++) {
                    const int n = n0 + wn * 64 + nj * 8 + 2 * t;
                    float2 v = make_float2(acc[mi][nj][2 * qh]     - ehs[n],
                                           acc[mi][nj][2 * qh + 1] - ehs[n + 1]);
                    *reinterpret_cast<float2*>(Srow + n) = v;
                }
            }
    }
}

// ---- pass 2: one warp per row — certified argmax + fp64 rescue of candidates ----
__global__ __launch_bounds__(256)
void rescue(const float* __restrict__ X, const float* __restrict__ E,
            float* __restrict__ out) {
    const int lane = threadIdx.x & 31;
    const int row  = blockIdx.x * 8 + (threadIdx.x >> 5);

    const float4* S4 = reinterpret_cast<const float4*>(g_S + (size_t)row * NCODES);
    float4 s4[8];
    float m1 = -3.4e38f;
#pragma unroll
    for (int j = 0; j < 8; j++) {
        s4[j] = S4[lane + 32 * j];
        m1 = fmaxf(m1, fmaxf(fmaxf(s4[j].x, s4[j].y), fmaxf(s4[j].z, s4[j].w)));
    }
#pragma unroll
    for (int off = 16; off > 0; off >>= 1)
        m1 = fmaxf(m1, __shfl_xor_sync(0xffffffffu, m1, off));

    const float4* X4 = reinterpret_cast<const float4*>(X + (size_t)row * D);
    float4 x0 = X4[lane], x1 = X4[lane + 32];
    float xsq = x0.x * x0.x + x0.y * x0.y + x0.z * x0.z + x0.w * x0.w
              + x1.x * x1.x + x1.y * x1.y + x1.z * x1.z + x1.w * x1.w;
#pragma unroll
    for (int off = 16; off > 0; off >>= 1)
        xsq += __shfl_xor_sync(0xffffffffu, xsq, off);

    const float maxEsq = __int_as_float(g_maxEsq_bits);
    const float M = 0.002f * sqrtf(xsq * maxEsq) + 0.03f;   // certified margin (2x bound + slack)
    const float thr = m1 - M;

    double bestv = -1e300;
    int    besti = 0;
#pragma unroll
    for (int j = 0; j < 8; j++) {
        const float sv[4] = { s4[j].x, s4[j].y, s4[j].z, s4[j].w };
#pragma unroll
        for (int c = 0; c < 4; c++) {
            unsigned bal = __ballot_sync(0xffffffffu, sv[c] >= thr);
            while (bal) {
                int b = __ffs(bal) - 1; bal &= bal - 1;
                int idx = 4 * b + 128 * j + c;
                const float4* E4r = reinterpret_cast<const float4*>(E + (size_t)idx * D);
                float4 e0 = E4r[lane], e1 = E4r[lane + 32];
                double sc =
                    (double)x0.x * e0.x + (double)x0.y * e0.y + (double)x0.z * e0.z + (double)x0.w * e0.w +
                    (double)x1.x * e1.x + (double)x1.y * e1.y + (double)x1.z * e1.z + (double)x1.w * e1.w
                    - 0.5 * ((double)e0.x * e0.x + (double)e0.y * e0.y + (double)e0.z * e0.z + (double)e0.w * e0.w +
                             (double)e1.x * e1.x + (double)e1.y * e1.y + (double)e1.z * e1.z + (double)e1.w * e1.w);
#pragma unroll
                for (int off = 16; off > 0; off >>= 1)
                    sc += __shfl_xor_sync(0xffffffffu, sc, off);
                if (sc > bestv || (sc == bestv && idx < besti)) { bestv = sc; besti = idx; }
            }
        }
    }

    const float4* Eb = reinterpret_cast<const float4*>(E + (size_t)besti * D);
    float4* O4 = reinterpret_cast<float4*>(out + (size_t)row * D);
    O4[lane]      = Eb[lane];
    O4[lane + 32] = Eb[lane + 32];
}

extern "C" void kernel_launch(void* const* d_in, const int* in_sizes, int n_in,
                              void* d_out, int out_size) {
    const float* x = (const float*)d_in[0];     // [16,1024,256] f32
    const float* E = (const float*)d_in[1];     // [1024,256]    f32
    float* out = (float*)d_out;

    init_kernel<<<1, 1>>>();
    e_half_kernel<<<(NCODES + 255) / 256, 256>>>(E);
    prep_e<<<NCODES * 16 / 256, 256>>>(E);
    prep_x<<<ROWS_TOTAL * 16 / 256, 256>>>(x);

    cudaFuncSetAttribute(vq_mma, cudaFuncAttributeMaxDynamicSharedMemorySize, SMEM_TOTAL);
    vq_mma<<<ROWS_TOTAL / BM, 256, SMEM_TOTAL>>>();

    rescue<<<ROWS_TOTAL / 8, 256>>>(x, E, out);
}